// round 12
// baseline (speedup 1.0000x reference)
#include <cuda_runtime.h>
#include <cuda_bf16.h>
#include <cstdint>
#include <math.h>

#define BB 32768
#define DD 256
#define NN 8192
#define RT 64          // rows per CTA tile
#define CT 64          // cols per B chunk
#define RCAP 96

// ---------------- scratch (__device__ globals; no allocation allowed) -------
__device__ __nv_bfloat16 g_eb[(size_t)NN * DD];    // bf16(e_hat)       4 MB
__device__ float         g_ehat[(size_t)NN * DD];  // e_hat fp32        8 MB
__device__ float g_part[512];

// ---------------- helpers ---------------------------------------------------
__device__ __forceinline__ uint32_t s2u(const void* p) {
    uint32_t a;
    asm("{ .reg .u64 t; cvta.to.shared.u64 t, %1; cvt.u32.u64 %0, t; }"
        : "=r"(a) : "l"(p));
    return a;
}
// smem tile layout: rows x 256 bf16 (512 B/row), 16B units XOR-swizzled
__device__ __forceinline__ uint32_t soff(int row, int u) {
    return (uint32_t)(row * 512 + ((u ^ (row & 7)) << 4));
}
__device__ __forceinline__ void cpa16(uint32_t s, const void* g) {
    asm volatile("cp.async.cg.shared.global [%0], [%1], 16;" :: "r"(s), "l"(g));
}
#define CPA_COMMIT() asm volatile("cp.async.commit_group;" ::: "memory")
#define CPA_WAIT0()  asm volatile("cp.async.wait_group 0;" ::: "memory")

#define LDSM4(r0, r1, r2, r3, addr) \
    asm volatile("ldmatrix.sync.aligned.m8n8.x4.shared.b16 {%0,%1,%2,%3}, [%4];" \
                 : "=r"(r0), "=r"(r1), "=r"(r2), "=r"(r3) : "r"(addr))

#define MMA16816(d, a0, a1, a2, a3, b0, b1) \
    asm volatile("mma.sync.aligned.m16n8k16.row.col.f32.bf16.bf16.f32 " \
                 "{%0,%1,%2,%3}, {%4,%5,%6,%7}, {%8,%9}, {%0,%1,%2,%3};" \
                 : "+f"((d)[0]), "+f"((d)[1]), "+f"((d)[2]), "+f"((d)[3]) \
                 : "r"(a0), "r"(a1), "r"(a2), "r"(a3), "r"(b0), "r"(b1))

// ---------------- prep: normalize embedding --------------------------------
__global__ void prep_e_kernel(const float* __restrict__ e) {
    int w = threadIdx.x >> 5, lane = threadIdx.x & 31;
    int n = blockIdx.x * 8 + w;
    float v[8];
    float ss = 0.f;
#pragma unroll
    for (int j = 0; j < 8; j++) {
        v[j] = e[(size_t)n * DD + j * 32 + lane];
        ss += v[j] * v[j];
    }
#pragma unroll
    for (int o = 16; o > 0; o >>= 1) ss += __shfl_xor_sync(0xffffffffu, ss, o);
    float inv = 1.f / fmaxf(sqrtf(ss), 1e-12f);
#pragma unroll
    for (int j = 0; j < 8; j++) {
        float h = v[j] * inv;
        g_ehat[(size_t)n * DD + j * 32 + lane] = h;
        g_eb[(size_t)n * DD + j * 32 + lane] = __float2bfloat16(h);
    }
}

// ---- fused HMMA bf16 GEMM + capture + rescore + epilogue + loss partial ---
// smem: A 32KB | B0 32KB | B1 32KB | marg 256 | cnt 256 | bestn 256 |
//       lists 24576  => 123648 B, occ 1
#define SM_B0 32768
#define SM_B1 65536
#define SM_MG 98304
#define SM_CC 98560
#define SM_BI 98816
#define SM_CL 99072
#define DYN_SMEM (99072 + RCAP * RT * 4)

__global__ void __launch_bounds__(256) gemm_kernel(const float* __restrict__ x,
                                                   const float* __restrict__ e,
                                                   float* __restrict__ out) {
    extern __shared__ char sm[];
    uint32_t sA = s2u(sm);
    int tid = threadIdx.x, wid = tid >> 5, lane = tid & 31;
    int rb = blockIdx.x * RT;
    float* marg_s = (float*)(sm + SM_MG);
    int* cnt_s = (int*)(sm + SM_CC);
    int* bestn_s = (int*)(sm + SM_BI);
    int* list_s = (int*)(sm + SM_CL);

    // -- prologue: B chunk 0 via cp.async; A tile fp32->bf16 in-CTA ----------
#pragma unroll
    for (int i = 0; i < 8; i++) {
        int q = tid + (i << 8);
        int row = q >> 5, u = q & 31;
        cpa16(sA + SM_B0 + soff(row, u), g_eb + (size_t)row * DD + u * 8);
    }
    CPA_COMMIT();

    {
        int row = tid >> 2, qq = tid & 3;      // 4 threads per row
        const float4* xp =
            (const float4*)(x + (size_t)(rb + row) * DD + qq * 64);
        float ss = 0.f;
#pragma unroll
        for (int j = 0; j < 8; j++) {
            float4 v0 = xp[2 * j], v1 = xp[2 * j + 1];
            ss += v0.x * v0.x + v0.y * v0.y + v0.z * v0.z + v0.w * v0.w +
                  v1.x * v1.x + v1.y * v1.y + v1.z * v1.z + v1.w * v1.w;
            uint4 st;
            __nv_bfloat162 h;
            h = __floats2bfloat162_rn(v0.x, v0.y); st.x = *(uint32_t*)&h;
            h = __floats2bfloat162_rn(v0.z, v0.w); st.y = *(uint32_t*)&h;
            h = __floats2bfloat162_rn(v1.x, v1.y); st.z = *(uint32_t*)&h;
            h = __floats2bfloat162_rn(v1.z, v1.w); st.w = *(uint32_t*)&h;
            *(uint4*)(sm + soff(row, qq * 8 + j)) = st;
        }
        ss += __shfl_xor_sync(0xffffffffu, ss, 1);
        ss += __shfl_xor_sync(0xffffffffu, ss, 2);
        if (qq == 0) {
            // bound on bf16-input dot error (~0.004*||x||) with >2x slack
            marg_s[row] = 0.01f * sqrtf(ss) + 0.02f;
            cnt_s[row] = 0;
        }
    }
    CPA_WAIT0();
    __syncthreads();

    int wm = wid >> 1, wn = wid & 1;           // 4 row-groups x 2 col-groups
    int g = lane >> 2, cpair = (lane & 3) * 2;

    // per-lane ldmatrix row/ku components
    int la7 = lane & 7;
    int rowA = wm * 16 + la7 + ((lane >> 3) & 1) * 8;
    int kuA_c = (lane >> 4);
    int rowB_c = wn * 32 + la7 + ((lane >> 4) & 1) * 8;  // + h*16
    int kuB_c = (lane >> 3) & 1;
    int r0 = wm * 16 + g, r1 = r0 + 8;
    float marg0 = marg_s[r0], marg1 = marg_s[r1];
    float rm0 = -3.4e38f, rm1 = -3.4e38f;      // per-warp running row max

    for (int t = 0; t < NN / CT; t++) {
        uint32_t sBc = sA + ((t & 1) ? SM_B1 : SM_B0);
        if (t < NN / CT - 1) {
            uint32_t sBn = sA + ((t & 1) ? SM_B0 : SM_B1);
            const __nv_bfloat16* gsrc = g_eb + (size_t)(t + 1) * CT * DD;
#pragma unroll
            for (int i = 0; i < 8; i++) {
                int q = tid + (i << 8);
                int row = q >> 5, u = q & 31;
                cpa16(sBn + soff(row, u), gsrc + (size_t)row * DD + u * 8);
            }
            CPA_COMMIT();
        }

        float acc[4][4];
#pragma unroll
        for (int ni = 0; ni < 4; ni++)
#pragma unroll
            for (int r = 0; r < 4; r++) acc[ni][r] = 0.f;

#pragma unroll
        for (int ks = 0; ks < 16; ks++) {
            int kb = ks * 2;
            uint32_t b[4][2];
#pragma unroll
            for (int h = 0; h < 2; h++) {
                uint32_t addr = sBc + soff(rowB_c + h * 16, kb + kuB_c);
                LDSM4(b[h * 2][0], b[h * 2][1], b[h * 2 + 1][0], b[h * 2 + 1][1],
                      addr);
            }
            uint32_t a0, a1, a2, a3;
            LDSM4(a0, a1, a2, a3, sA + soff(rowA, kb + kuA_c));
#pragma unroll
            for (int ni = 0; ni < 4; ni++)
                MMA16816(acc[ni], a0, a1, a2, a3, b[ni][0], b[ni][1]);
        }

        // ---- capture: register running-max threshold, smem lists -----------
        float m0 = -3.4e38f, m1 = -3.4e38f;
#pragma unroll
        for (int ni = 0; ni < 4; ni++) {
            m0 = fmaxf(m0, fmaxf(acc[ni][0], acc[ni][1]));
            m1 = fmaxf(m1, fmaxf(acc[ni][2], acc[ni][3]));
        }
        m0 = fmaxf(m0, __shfl_xor_sync(0xffffffffu, m0, 1));
        m0 = fmaxf(m0, __shfl_xor_sync(0xffffffffu, m0, 2));
        m1 = fmaxf(m1, __shfl_xor_sync(0xffffffffu, m1, 1));
        m1 = fmaxf(m1, __shfl_xor_sync(0xffffffffu, m1, 2));
        rm0 = fmaxf(rm0, m0);
        rm1 = fmaxf(rm1, m1);
        float thr0 = rm0 - marg0;
        float thr1 = rm1 - marg1;
        int ncol = t * CT + wn * 32 + cpair;
        if (m0 > thr0) {
#pragma unroll
            for (int ni = 0; ni < 4; ni++) {
                if (acc[ni][0] > thr0) {
                    int p = atomicAdd(&cnt_s[r0], 1);
                    if (p < RCAP) list_s[r0 * RCAP + p] = ncol + ni * 8;
                }
                if (acc[ni][1] > thr0) {
                    int p = atomicAdd(&cnt_s[r0], 1);
                    if (p < RCAP) list_s[r0 * RCAP + p] = ncol + ni * 8 + 1;
                }
            }
        }
        if (m1 > thr1) {
#pragma unroll
            for (int ni = 0; ni < 4; ni++) {
                if (acc[ni][2] > thr1) {
                    int p = atomicAdd(&cnt_s[r1], 1);
                    if (p < RCAP) list_s[r1 * RCAP + p] = ncol + ni * 8;
                }
                if (acc[ni][3] > thr1) {
                    int p = atomicAdd(&cnt_s[r1], 1);
                    if (p < RCAP) list_s[r1 * RCAP + p] = ncol + ni * 8 + 1;
                }
            }
        }

        if (t < NN / CT - 1) CPA_WAIT0();
        __syncthreads();   // B prefetch landed; safe to swap buffers
    }

    // ---- tail 1: exact fp32 rescore (one warp per row, 8 rows/warp) --------
    for (int rr = wid; rr < RT; rr += 8) {
        int row = rb + rr;
        const float4* xp = (const float4*)(x + (size_t)row * DD);
        float4 xa = xp[lane * 2], xb2 = xp[lane * 2 + 1];
        float bestv = -3.4e38f;
        int bestn = 0;
        int c = cnt_s[rr];
        if (c <= RCAP) {
            for (int i = 0; i < c; i++) {
                int n = list_s[rr * RCAP + i];
                const float4* ep = (const float4*)(g_ehat + (size_t)n * DD);
                float4 e0 = ep[lane * 2], e1 = ep[lane * 2 + 1];
                float p = xa.x * e0.x + xa.y * e0.y + xa.z * e0.z + xa.w * e0.w +
                          xb2.x * e1.x + xb2.y * e1.y + xb2.z * e1.z +
                          xb2.w * e1.w;
#pragma unroll
                for (int o = 16; o > 0; o >>= 1)
                    p += __shfl_xor_sync(0xffffffffu, p, o);
                if (p > bestv || (p == bestv && n < bestn)) { bestv = p; bestn = n; }
            }
        } else {
            // overflow fallback (provably correct, ~never taken): full scan
            for (int n = 0; n < NN; n++) {
                const float4* ep = (const float4*)(g_ehat + (size_t)n * DD);
                float4 e0 = ep[lane * 2], e1 = ep[lane * 2 + 1];
                float p = xa.x * e0.x + xa.y * e0.y + xa.z * e0.z + xa.w * e0.w +
                          xb2.x * e1.x + xb2.y * e1.y + xb2.z * e1.z +
                          xb2.w * e1.w;
#pragma unroll
                for (int o = 16; o > 0; o >>= 1)
                    p += __shfl_xor_sync(0xffffffffu, p, o);
                if (p > bestv || (p == bestv && n < bestn)) { bestv = p; bestn = n; }
            }
        }
        if (lane == 0) bestn_s[rr] = bestn;
    }
    __syncthreads();

    // ---- tail 2: projection / x_q / commit epilogue (warp per row) ---------
    for (int rr = wid; rr < RT; rr += 8) {
        int row = rb + rr;
        int idx = bestn_s[rr];
        const float4* xp = (const float4*)(x + (size_t)row * DD);
        const float4* ep = (const float4*)(e + (size_t)idx * DD);
        float4 xa = xp[lane * 2], xb2 = xp[lane * 2 + 1];
        float4 ea = ep[lane * 2], eb2 = ep[lane * 2 + 1];
        float s1 = xa.x * ea.x + xa.y * ea.y + xa.z * ea.z + xa.w * ea.w +
                   xb2.x * eb2.x + xb2.y * eb2.y + xb2.z * eb2.z + xb2.w * eb2.w;
        float s2 = ea.x * ea.x + ea.y * ea.y + ea.z * ea.z + ea.w * ea.w +
                   eb2.x * eb2.x + eb2.y * eb2.y + eb2.z * eb2.z + eb2.w * eb2.w;
        float s3 = xa.x * xa.x + xa.y * xa.y + xa.z * xa.z + xa.w * xa.w +
                   xb2.x * xb2.x + xb2.y * xb2.y + xb2.z * xb2.z + xb2.w * xb2.w;
#pragma unroll
        for (int o = 16; o > 0; o >>= 1) {
            s1 += __shfl_xor_sync(0xffffffffu, s1, o);
            s2 += __shfl_xor_sync(0xffffffffu, s2, o);
            s3 += __shfl_xor_sync(0xffffffffu, s3, o);
        }
        float dot = s1, csq = s2, xsq = s3;
        float scalar = dot / (csq + 1e-8f);
        float4 o0, o1;
        o0.x = xa.x + (scalar * ea.x - xa.x);
        o0.y = xa.y + (scalar * ea.y - xa.y);
        o0.z = xa.z + (scalar * ea.z - xa.z);
        o0.w = xa.w + (scalar * ea.w - xa.w);
        o1.x = xb2.x + (scalar * eb2.x - xb2.x);
        o1.y = xb2.y + (scalar * eb2.y - xb2.y);
        o1.z = xb2.z + (scalar * eb2.z - xb2.z);
        o1.w = xb2.w + (scalar * eb2.w - xb2.w);
        float4* op = (float4*)(out + (size_t)row * DD);
        op[lane * 2] = o0;
        op[lane * 2 + 1] = o1;
        if (lane == 0) {
            float pn = fabsf(scalar) * sqrtf(csq);
            float commit = (scalar * dot) /
                           (fmaxf(pn, 1e-8f) * fmaxf(sqrtf(xsq), 1e-8f));
            marg_s[rr] = 1.0f - commit;        // reuse marg_s as commit scratch
            out[(size_t)BB * DD + 1 + row] = (float)idx;
            out[(size_t)BB * DD + 1 + BB + row] = scalar;
        }
    }
    __syncthreads();

    // ---- loss partial: deterministic fixed-order sum of this CTA's rows ----
    if (tid == 0) {
        float s = 0.f;
#pragma unroll
        for (int i = 0; i < RT; i++) s += marg_s[i];
        g_part[blockIdx.x] = s;
    }
}

// ---------------- loss finalize: deterministic tree over 512 parts ---------
__global__ void loss_fin_kernel(float* __restrict__ out) {
    __shared__ float sh[256];
    int t = threadIdx.x;
    sh[t] = g_part[t] + g_part[t + 256];
    __syncthreads();
    for (int o = 128; o > 0; o >>= 1) {
        if (t < o) sh[t] += sh[t + o];
        __syncthreads();
    }
    if (t == 0) out[(size_t)BB * DD] = 0.25f * sh[0] / (float)BB;
}

// ---------------------------------------------------------------------------
extern "C" void kernel_launch(void* const* d_in, const int* in_sizes, int n_in,
                              void* d_out, int out_size) {
    const float* x = (const float*)d_in[0];
    const float* e = (const float*)d_in[1];
    float* out = (float*)d_out;

    cudaFuncSetAttribute(gemm_kernel,
                         cudaFuncAttributeMaxDynamicSharedMemorySize, DYN_SMEM);
    prep_e_kernel<<<NN / 8, 256>>>(e);
    gemm_kernel<<<BB / RT, 256, DYN_SMEM>>>(x, e, out);
    loss_fin_kernel<<<1, 256>>>(out);
}

// round 14
// speedup vs baseline: 1.8411x; 1.8411x over previous
#include <cuda_runtime.h>
#include <cuda_bf16.h>
#include <cstdint>
#include <math.h>

#define BB 32768
#define DD 256
#define NN 8192
#define RT 64          // rows per CTA tile
#define CT 64          // cols per B chunk
#define RCAP 128

// ---------------- scratch (__device__ globals; no allocation allowed) -------
__device__ __nv_bfloat16 g_eb[(size_t)NN * DD];    // bf16(e_hat)       4 MB
__device__ float         g_ehat[(size_t)NN * DD];  // e_hat fp32        8 MB
__device__ float g_part[512];

// ---------------- helpers ---------------------------------------------------
__device__ __forceinline__ unsigned ford(float f) {
    unsigned u = __float_as_uint(f);
    return (u & 0x80000000u) ? ~u : (u | 0x80000000u);
}
__device__ __forceinline__ float unford(unsigned u) {
    unsigned v = (u & 0x80000000u) ? (u & 0x7fffffffu) : ~u;
    return __uint_as_float(v);
}
__device__ __forceinline__ uint32_t s2u(const void* p) {
    uint32_t a;
    asm("{ .reg .u64 t; cvta.to.shared.u64 t, %1; cvt.u32.u64 %0, t; }"
        : "=r"(a) : "l"(p));
    return a;
}
// smem tile layout: rows x 256 bf16 (512 B/row), 16B units XOR-swizzled
__device__ __forceinline__ uint32_t soff(int row, int u) {
    return (uint32_t)(row * 512 + ((u ^ (row & 7)) << 4));
}
__device__ __forceinline__ void cpa16(uint32_t s, const void* g) {
    asm volatile("cp.async.cg.shared.global [%0], [%1], 16;" :: "r"(s), "l"(g));
}
#define CPA_COMMIT() asm volatile("cp.async.commit_group;" ::: "memory")
#define CPA_WAIT0()  asm volatile("cp.async.wait_group 0;" ::: "memory")

#define LDSM4(r0, r1, r2, r3, addr) \
    asm volatile("ldmatrix.sync.aligned.m8n8.x4.shared.b16 {%0,%1,%2,%3}, [%4];" \
                 : "=r"(r0), "=r"(r1), "=r"(r2), "=r"(r3) : "r"(addr))

#define MMA16816(d, a0, a1, a2, a3, b0, b1) \
    asm volatile("mma.sync.aligned.m16n8k16.row.col.f32.bf16.bf16.f32 " \
                 "{%0,%1,%2,%3}, {%4,%5,%6,%7}, {%8,%9}, {%0,%1,%2,%3};" \
                 : "+f"((d)[0]), "+f"((d)[1]), "+f"((d)[2]), "+f"((d)[3]) \
                 : "r"(a0), "r"(a1), "r"(a2), "r"(a3), "r"(b0), "r"(b1))

// ---------------- prep: normalize embedding --------------------------------
__global__ void prep_e_kernel(const float* __restrict__ e) {
    int w = threadIdx.x >> 5, lane = threadIdx.x & 31;
    int n = blockIdx.x * 8 + w;
    float v[8];
    float ss = 0.f;
#pragma unroll
    for (int j = 0; j < 8; j++) {
        v[j] = e[(size_t)n * DD + j * 32 + lane];
        ss += v[j] * v[j];
    }
#pragma unroll
    for (int o = 16; o > 0; o >>= 1) ss += __shfl_xor_sync(0xffffffffu, ss, o);
    float inv = 1.f / fmaxf(sqrtf(ss), 1e-12f);
#pragma unroll
    for (int j = 0; j < 8; j++) {
        float h = v[j] * inv;
        g_ehat[(size_t)n * DD + j * 32 + lane] = h;
        g_eb[(size_t)n * DD + j * 32 + lane] = __float2bfloat16(h);
    }
}

// ---- fused HMMA bf16 GEMM + capture + rescore + epilogue + loss partial ---
// smem: A 32KB | B0 32KB | B1 32KB | rowmax 256 | marg 256 | cnt 256 |
//       besti 256 | lists 32KB  => 132096 B, occ 1
#define SM_B0 32768
#define SM_B1 65536
#define SM_RM 98304
#define SM_MG 98560
#define SM_CC 98816
#define SM_BI 99072
#define SM_CL 99328
#define DYN_SMEM (99328 + RCAP * RT * 4)

__global__ void __launch_bounds__(256) gemm_kernel(const float* __restrict__ x,
                                                   const float* __restrict__ e,
                                                   float* __restrict__ out) {
    extern __shared__ char sm[];
    uint32_t sA = s2u(sm);
    int tid = threadIdx.x, wid = tid >> 5, lane = tid & 31;
    int rb = blockIdx.x * RT;
    unsigned* rowmax_s = (unsigned*)(sm + SM_RM);
    float* marg_s = (float*)(sm + SM_MG);
    int* cnt_s = (int*)(sm + SM_CC);
    int* bestn_s = (int*)(sm + SM_BI);
    int* list_s = (int*)(sm + SM_CL);

    // -- prologue: B chunk 0 via cp.async; A tile fp32->bf16 in-CTA ----------
#pragma unroll
    for (int i = 0; i < 8; i++) {
        int q = tid + (i << 8);
        int row = q >> 5, u = q & 31;
        cpa16(sA + SM_B0 + soff(row, u), g_eb + (size_t)row * DD + u * 8);
    }
    CPA_COMMIT();

    {
        int row = tid >> 2, qq = tid & 3;      // 4 threads per row
        const float4* xp =
            (const float4*)(x + (size_t)(rb + row) * DD + qq * 64);
        float ss = 0.f;
#pragma unroll
        for (int j = 0; j < 8; j++) {
            float4 v0 = xp[2 * j], v1 = xp[2 * j + 1];
            ss += v0.x * v0.x + v0.y * v0.y + v0.z * v0.z + v0.w * v0.w +
                  v1.x * v1.x + v1.y * v1.y + v1.z * v1.z + v1.w * v1.w;
            uint4 st;
            __nv_bfloat162 h;
            h = __floats2bfloat162_rn(v0.x, v0.y); st.x = *(uint32_t*)&h;
            h = __floats2bfloat162_rn(v0.z, v0.w); st.y = *(uint32_t*)&h;
            h = __floats2bfloat162_rn(v1.x, v1.y); st.z = *(uint32_t*)&h;
            h = __floats2bfloat162_rn(v1.z, v1.w); st.w = *(uint32_t*)&h;
            *(uint4*)(sm + soff(row, qq * 8 + j)) = st;
        }
        ss += __shfl_xor_sync(0xffffffffu, ss, 1);
        ss += __shfl_xor_sync(0xffffffffu, ss, 2);
        if (qq == 0) {
            // bound on bf16-input dot error (~0.004*||x||) with >2x slack
            marg_s[row] = 0.01f * sqrtf(ss) + 0.02f;
            rowmax_s[row] = ford(-3.4e38f);
            cnt_s[row] = 0;
        }
    }
    CPA_WAIT0();
    __syncthreads();

    int wm = wid >> 1, wn = wid & 1;           // 4 row-groups x 2 col-groups
    int g = lane >> 2, cpair = (lane & 3) * 2;

    // per-lane ldmatrix row/ku components
    int la7 = lane & 7;
    int rowA = wm * 16 + la7 + ((lane >> 3) & 1) * 8;
    int kuA_c = (lane >> 4);
    int rowB_c = wn * 32 + la7 + ((lane >> 4) & 1) * 8;  // + h*16
    int kuB_c = (lane >> 3) & 1;
    int r0 = wm * 16 + g, r1 = r0 + 8;
    float marg0 = marg_s[r0], marg1 = marg_s[r1];

    for (int t = 0; t < NN / CT; t++) {
        uint32_t sBc = sA + ((t & 1) ? SM_B1 : SM_B0);
        if (t < NN / CT - 1) {
            uint32_t sBn = sA + ((t & 1) ? SM_B0 : SM_B1);
            const __nv_bfloat16* gsrc = g_eb + (size_t)(t + 1) * CT * DD;
#pragma unroll
            for (int i = 0; i < 8; i++) {
                int q = tid + (i << 8);
                int row = q >> 5, u = q & 31;
                cpa16(sBn + soff(row, u), gsrc + (size_t)row * DD + u * 8);
            }
            CPA_COMMIT();
        }

        float acc[4][4];
#pragma unroll
        for (int ni = 0; ni < 4; ni++)
#pragma unroll
            for (int r = 0; r < 4; r++) acc[ni][r] = 0.f;

#pragma unroll
        for (int ks = 0; ks < 16; ks++) {
            int kb = ks * 2;
            uint32_t b[4][2];
#pragma unroll
            for (int h = 0; h < 2; h++) {
                uint32_t addr = sBc + soff(rowB_c + h * 16, kb + kuB_c);
                LDSM4(b[h * 2][0], b[h * 2][1], b[h * 2 + 1][0], b[h * 2 + 1][1],
                      addr);
            }
            uint32_t a0, a1, a2, a3;
            LDSM4(a0, a1, a2, a3, sA + soff(rowA, kb + kuA_c));
#pragma unroll
            for (int ni = 0; ni < 4; ni++)
                MMA16816(acc[ni], a0, a1, a2, a3, b[ni][0], b[ni][1]);
        }

        // ---- phase A: per-row tile max -> smem rowmax (CTA-wide, tight) ----
        float m0 = -3.4e38f, m1 = -3.4e38f;
#pragma unroll
        for (int ni = 0; ni < 4; ni++) {
            m0 = fmaxf(m0, fmaxf(acc[ni][0], acc[ni][1]));
            m1 = fmaxf(m1, fmaxf(acc[ni][2], acc[ni][3]));
        }
        m0 = fmaxf(m0, __shfl_xor_sync(0xffffffffu, m0, 1));
        m0 = fmaxf(m0, __shfl_xor_sync(0xffffffffu, m0, 2));
        m1 = fmaxf(m1, __shfl_xor_sync(0xffffffffu, m1, 1));
        m1 = fmaxf(m1, __shfl_xor_sync(0xffffffffu, m1, 2));
        if ((lane & 3) == 0) {
            atomicMax(&rowmax_s[r0], ford(m0));
            atomicMax(&rowmax_s[r1], ford(m1));
        }
        if (t < NN / CT - 1) CPA_WAIT0();
        __syncthreads();   // rowmax visible to all; B prefetch landed

        // ---- phase B: append candidates above (rowmax - margin) ------------
        int ncol = t * CT + wn * 32 + cpair;
        float thr0 = unford(rowmax_s[r0]) - marg0;
        float thr1 = unford(rowmax_s[r1]) - marg1;
        if (m0 > thr0) {
#pragma unroll
            for (int ni = 0; ni < 4; ni++) {
                if (acc[ni][0] > thr0) {
                    int p = atomicAdd(&cnt_s[r0], 1);
                    if (p < RCAP) list_s[r0 * RCAP + p] = ncol + ni * 8;
                }
                if (acc[ni][1] > thr0) {
                    int p = atomicAdd(&cnt_s[r0], 1);
                    if (p < RCAP) list_s[r0 * RCAP + p] = ncol + ni * 8 + 1;
                }
            }
        }
        if (m1 > thr1) {
#pragma unroll
            for (int ni = 0; ni < 4; ni++) {
                if (acc[ni][2] > thr1) {
                    int p = atomicAdd(&cnt_s[r1], 1);
                    if (p < RCAP) list_s[r1 * RCAP + p] = ncol + ni * 8;
                }
                if (acc[ni][3] > thr1) {
                    int p = atomicAdd(&cnt_s[r1], 1);
                    if (p < RCAP) list_s[r1 * RCAP + p] = ncol + ni * 8 + 1;
                }
            }
        }
    }
    __syncthreads();   // lists complete

    // ---- tail 1: exact fp32 rescore (one warp per row, 8 rows/warp) --------
    for (int rr = wid; rr < RT; rr += 8) {
        int row = rb + rr;
        const float4* xp = (const float4*)(x + (size_t)row * DD);
        float4 xa = xp[lane * 2], xb2 = xp[lane * 2 + 1];
        float bestv = -3.4e38f;
        int bestn = 0;
        int c = cnt_s[rr];
        if (c <= RCAP) {
            for (int i = 0; i < c; i++) {
                int n = list_s[rr * RCAP + i];
                const float4* ep = (const float4*)(g_ehat + (size_t)n * DD);
                float4 e0 = ep[lane * 2], e1 = ep[lane * 2 + 1];
                float p = xa.x * e0.x + xa.y * e0.y + xa.z * e0.z + xa.w * e0.w +
                          xb2.x * e1.x + xb2.y * e1.y + xb2.z * e1.z +
                          xb2.w * e1.w;
#pragma unroll
                for (int o = 16; o > 0; o >>= 1)
                    p += __shfl_xor_sync(0xffffffffu, p, o);
                if (p > bestv || (p == bestv && n < bestn)) { bestv = p; bestn = n; }
            }
        } else {
            // overflow fallback (provably correct, ~never taken): full scan
            for (int n = 0; n < NN; n++) {
                const float4* ep = (const float4*)(g_ehat + (size_t)n * DD);
                float4 e0 = ep[lane * 2], e1 = ep[lane * 2 + 1];
                float p = xa.x * e0.x + xa.y * e0.y + xa.z * e0.z + xa.w * e0.w +
                          xb2.x * e1.x + xb2.y * e1.y + xb2.z * e1.z +
                          xb2.w * e1.w;
#pragma unroll
                for (int o = 16; o > 0; o >>= 1)
                    p += __shfl_xor_sync(0xffffffffu, p, o);
                if (p > bestv || (p == bestv && n < bestn)) { bestv = p; bestn = n; }
            }
        }
        if (lane == 0) bestn_s[rr] = bestn;
    }
    __syncthreads();

    // ---- tail 2: projection / x_q / commit epilogue (warp per row) ---------
    for (int rr = wid; rr < RT; rr += 8) {
        int row = rb + rr;
        int idx = bestn_s[rr];
        const float4* xp = (const float4*)(x + (size_t)row * DD);
        const float4* ep = (const float4*)(e + (size_t)idx * DD);
        float4 xa = xp[lane * 2], xb2 = xp[lane * 2 + 1];
        float4 ea = ep[lane * 2], eb2 = ep[lane * 2 + 1];
        float s1 = xa.x * ea.x + xa.y * ea.y + xa.z * ea.z + xa.w * ea.w +
                   xb2.x * eb2.x + xb2.y * eb2.y + xb2.z * eb2.z + xb2.w * eb2.w;
        float s2 = ea.x * ea.x + ea.y * ea.y + ea.z * ea.z + ea.w * ea.w +
                   eb2.x * eb2.x + eb2.y * eb2.y + eb2.z * eb2.z + eb2.w * eb2.w;
        float s3 = xa.x * xa.x + xa.y * xa.y + xa.z * xa.z + xa.w * xa.w +
                   xb2.x * xb2.x + xb2.y * xb2.y + xb2.z * xb2.z + xb2.w * xb2.w;
#pragma unroll
        for (int o = 16; o > 0; o >>= 1) {
            s1 += __shfl_xor_sync(0xffffffffu, s1, o);
            s2 += __shfl_xor_sync(0xffffffffu, s2, o);
            s3 += __shfl_xor_sync(0xffffffffu, s3, o);
        }
        float dot = s1, csq = s2, xsq = s3;
        float scalar = dot / (csq + 1e-8f);
        float4 o0, o1;
        o0.x = xa.x + (scalar * ea.x - xa.x);
        o0.y = xa.y + (scalar * ea.y - xa.y);
        o0.z = xa.z + (scalar * ea.z - xa.z);
        o0.w = xa.w + (scalar * ea.w - xa.w);
        o1.x = xb2.x + (scalar * eb2.x - xb2.x);
        o1.y = xb2.y + (scalar * eb2.y - xb2.y);
        o1.z = xb2.z + (scalar * eb2.z - xb2.z);
        o1.w = xb2.w + (scalar * eb2.w - xb2.w);
        float4* op = (float4*)(out + (size_t)row * DD);
        op[lane * 2] = o0;
        op[lane * 2 + 1] = o1;
        if (lane == 0) {
            float pn = fabsf(scalar) * sqrtf(csq);
            float commit = (scalar * dot) /
                           (fmaxf(pn, 1e-8f) * fmaxf(sqrtf(xsq), 1e-8f));
            marg_s[rr] = 1.0f - commit;        // reuse marg_s as commit scratch
            out[(size_t)BB * DD + 1 + row] = (float)idx;
            out[(size_t)BB * DD + 1 + BB + row] = scalar;
        }
    }
    __syncthreads();

    // ---- loss partial: deterministic fixed-order sum of this CTA's rows ----
    if (tid == 0) {
        float s = 0.f;
#pragma unroll
        for (int i = 0; i < RT; i++) s += marg_s[i];
        g_part[blockIdx.x] = s;
    }
}

// ---------------- loss finalize: deterministic tree over 512 parts ---------
__global__ void loss_fin_kernel(float* __restrict__ out) {
    __shared__ float sh[256];
    int t = threadIdx.x;
    sh[t] = g_part[t] + g_part[t + 256];
    __syncthreads();
    for (int o = 128; o > 0; o >>= 1) {
        if (t < o) sh[t] += sh[t + o];
        __syncthreads();
    }
    if (t == 0) out[(size_t)BB * DD] = 0.25f * sh[0] / (float)BB;
}

// ---------------------------------------------------------------------------
extern "C" void kernel_launch(void* const* d_in, const int* in_sizes, int n_in,
                              void* d_out, int out_size) {
    const float* x = (const float*)d_in[0];
    const float* e = (const float*)d_in[1];
    float* out = (float*)d_out;

    cudaFuncSetAttribute(gemm_kernel,
                         cudaFuncAttributeMaxDynamicSharedMemorySize, DYN_SMEM);
    prep_e_kernel<<<NN / 8, 256>>>(e);
    gemm_kernel<<<BB / RT, 256, DYN_SMEM>>>(x, e, out);
    loss_fin_kernel<<<1, 256>>>(out);
}

// round 15
// speedup vs baseline: 2.4126x; 1.3104x over previous
#include <cuda_runtime.h>
#include <cuda_bf16.h>
#include <cstdint>
#include <math.h>

#define BB 32768
#define DD 256
#define NN 8192
#define RT 64          // rows per CTA tile
#define CT 64          // cols per B chunk
#define RCAP 60

// ---------------- scratch (__device__ globals; no allocation allowed) -------
__device__ __nv_bfloat16 g_eb[(size_t)NN * DD];    // bf16(e_hat)       4 MB
__device__ float         g_ehat[(size_t)NN * DD];  // e_hat fp32        8 MB
__device__ float g_part[512];

// ---------------- helpers ---------------------------------------------------
__device__ __forceinline__ unsigned ford(float f) {
    unsigned u = __float_as_uint(f);
    return (u & 0x80000000u) ? ~u : (u | 0x80000000u);
}
__device__ __forceinline__ float unford(unsigned u) {
    unsigned v = (u & 0x80000000u) ? (u & 0x7fffffffu) : ~u;
    return __uint_as_float(v);
}
__device__ __forceinline__ uint32_t s2u(const void* p) {
    uint32_t a;
    asm("{ .reg .u64 t; cvta.to.shared.u64 t, %1; cvt.u32.u64 %0, t; }"
        : "=r"(a) : "l"(p));
    return a;
}
// smem tile layout: rows x 256 bf16 (512 B/row), 16B units XOR-swizzled
__device__ __forceinline__ uint32_t soff(int row, int u) {
    return (uint32_t)(row * 512 + ((u ^ (row & 7)) << 4));
}
__device__ __forceinline__ void cpa16(uint32_t s, const void* g) {
    asm volatile("cp.async.cg.shared.global [%0], [%1], 16;" :: "r"(s), "l"(g));
}
#define CPA_COMMIT() asm volatile("cp.async.commit_group;" ::: "memory")
#define CPA_WAIT0()  asm volatile("cp.async.wait_group 0;" ::: "memory")

#define LDSM4(r0, r1, r2, r3, addr) \
    asm volatile("ldmatrix.sync.aligned.m8n8.x4.shared.b16 {%0,%1,%2,%3}, [%4];" \
                 : "=r"(r0), "=r"(r1), "=r"(r2), "=r"(r3) : "r"(addr))

#define MMA16816(d, a0, a1, a2, a3, b0, b1) \
    asm volatile("mma.sync.aligned.m16n8k16.row.col.f32.bf16.bf16.f32 " \
                 "{%0,%1,%2,%3}, {%4,%5,%6,%7}, {%8,%9}, {%0,%1,%2,%3};" \
                 : "+f"((d)[0]), "+f"((d)[1]), "+f"((d)[2]), "+f"((d)[3]) \
                 : "r"(a0), "r"(a1), "r"(a2), "r"(a3), "r"(b0), "r"(b1))

// ---------------- prep: normalize embedding --------------------------------
__global__ void prep_e_kernel(const float* __restrict__ e) {
    int w = threadIdx.x >> 5, lane = threadIdx.x & 31;
    int n = blockIdx.x * 8 + w;
    float v[8];
    float ss = 0.f;
#pragma unroll
    for (int j = 0; j < 8; j++) {
        v[j] = e[(size_t)n * DD + j * 32 + lane];
        ss += v[j] * v[j];
    }
#pragma unroll
    for (int o = 16; o > 0; o >>= 1) ss += __shfl_xor_sync(0xffffffffu, ss, o);
    float inv = 1.f / fmaxf(sqrtf(ss), 1e-12f);
#pragma unroll
    for (int j = 0; j < 8; j++) {
        float h = v[j] * inv;
        g_ehat[(size_t)n * DD + j * 32 + lane] = h;
        g_eb[(size_t)n * DD + j * 32 + lane] = __float2bfloat16(h);
    }
}

// ---- fused HMMA bf16 GEMM + capture + rescore + epilogue + loss partial ---
// smem: A 32KB | B0 32KB | B1 32KB | marg 256 | rowmax 256 | cnt 256 |
//       bestn 256 | lists 15360  => 114688 B (identical to the 594.5 config)
#define SM_B0 32768
#define SM_B1 65536
#define SM_RM 98304
#define SM_MG 98560
#define SM_CC 98816
#define SM_BI 99072
#define SM_CL 99328
#define DYN_SMEM (99328 + RCAP * RT * 4)

__global__ void __launch_bounds__(256) gemm_kernel(const float* __restrict__ x,
                                                   const float* __restrict__ e,
                                                   float* __restrict__ out) {
    extern __shared__ char sm[];
    uint32_t sA = s2u(sm);
    int tid = threadIdx.x, wid = tid >> 5, lane = tid & 31;
    int rb = blockIdx.x * RT;
    unsigned* rowmax_s = (unsigned*)(sm + SM_RM);
    float* marg_s = (float*)(sm + SM_MG);
    int* cnt_s = (int*)(sm + SM_CC);
    int* bestn_s = (int*)(sm + SM_BI);
    int* list_s = (int*)(sm + SM_CL);

    // -- prologue: B chunk 0 via cp.async; A tile fp32->bf16 in-CTA ----------
#pragma unroll
    for (int i = 0; i < 8; i++) {
        int q = tid + (i << 8);
        int row = q >> 5, u = q & 31;
        cpa16(sA + SM_B0 + soff(row, u), g_eb + (size_t)row * DD + u * 8);
    }
    CPA_COMMIT();

    {
        int row = tid >> 2, qq = tid & 3;      // 4 threads per row
        const float4* xp =
            (const float4*)(x + (size_t)(rb + row) * DD + qq * 64);
        float ss = 0.f;
#pragma unroll
        for (int j = 0; j < 8; j++) {
            float4 v0 = xp[2 * j], v1 = xp[2 * j + 1];
            ss += v0.x * v0.x + v0.y * v0.y + v0.z * v0.z + v0.w * v0.w +
                  v1.x * v1.x + v1.y * v1.y + v1.z * v1.z + v1.w * v1.w;
            uint4 st;
            __nv_bfloat162 h;
            h = __floats2bfloat162_rn(v0.x, v0.y); st.x = *(uint32_t*)&h;
            h = __floats2bfloat162_rn(v0.z, v0.w); st.y = *(uint32_t*)&h;
            h = __floats2bfloat162_rn(v1.x, v1.y); st.z = *(uint32_t*)&h;
            h = __floats2bfloat162_rn(v1.z, v1.w); st.w = *(uint32_t*)&h;
            *(uint4*)(sm + soff(row, qq * 8 + j)) = st;
        }
        ss += __shfl_xor_sync(0xffffffffu, ss, 1);
        ss += __shfl_xor_sync(0xffffffffu, ss, 2);
        if (qq == 0) {
            // bound on bf16-input dot error (~0.004*||x||) with >2x slack
            marg_s[row] = 0.01f * sqrtf(ss) + 0.02f;
            rowmax_s[row] = ford(-3.4e38f);
            cnt_s[row] = 0;
        }
    }
    CPA_WAIT0();
    __syncthreads();

    int wm = wid >> 1, wn = wid & 1;           // 4 row-groups x 2 col-groups
    int g = lane >> 2, cpair = (lane & 3) * 2;

    // per-lane ldmatrix row/ku components
    int la7 = lane & 7;
    int rowA = wm * 16 + la7 + ((lane >> 3) & 1) * 8;
    int kuA_c = (lane >> 4);
    int rowB_c = wn * 32 + la7 + ((lane >> 4) & 1) * 8;  // + h*16
    int kuB_c = (lane >> 3) & 1;
    int r0 = wm * 16 + g, r1 = r0 + 8;

    for (int t = 0; t < NN / CT; t++) {
        uint32_t sBc = sA + ((t & 1) ? SM_B1 : SM_B0);
        if (t < NN / CT - 1) {
            uint32_t sBn = sA + ((t & 1) ? SM_B0 : SM_B1);
            const __nv_bfloat16* gsrc = g_eb + (size_t)(t + 1) * CT * DD;
#pragma unroll
            for (int i = 0; i < 8; i++) {
                int q = tid + (i << 8);
                int row = q >> 5, u = q & 31;
                cpa16(sBn + soff(row, u), gsrc + (size_t)row * DD + u * 8);
            }
            CPA_COMMIT();
        }

        float acc[4][4];
#pragma unroll
        for (int ni = 0; ni < 4; ni++)
#pragma unroll
            for (int r = 0; r < 4; r++) acc[ni][r] = 0.f;

#pragma unroll
        for (int ks = 0; ks < 16; ks++) {
            int kb = ks * 2;
            uint32_t b[4][2];
#pragma unroll
            for (int h = 0; h < 2; h++) {
                uint32_t addr = sBc + soff(rowB_c + h * 16, kb + kuB_c);
                LDSM4(b[h * 2][0], b[h * 2][1], b[h * 2 + 1][0], b[h * 2 + 1][1],
                      addr);
            }
            uint32_t a0, a1, a2, a3;
            LDSM4(a0, a1, a2, a3, sA + soff(rowA, kb + kuA_c));
#pragma unroll
            for (int ni = 0; ni < 4; ni++)
                MMA16816(acc[ni], a0, a1, a2, a3, b[ni][0], b[ni][1]);
        }

        // ---- phase A: per-row tile max -> smem rowmax ----------------------
        float m0 = -3.4e38f, m1 = -3.4e38f;
#pragma unroll
        for (int ni = 0; ni < 4; ni++) {
            m0 = fmaxf(m0, fmaxf(acc[ni][0], acc[ni][1]));
            m1 = fmaxf(m1, fmaxf(acc[ni][2], acc[ni][3]));
        }
        m0 = fmaxf(m0, __shfl_xor_sync(0xffffffffu, m0, 1));
        m0 = fmaxf(m0, __shfl_xor_sync(0xffffffffu, m0, 2));
        m1 = fmaxf(m1, __shfl_xor_sync(0xffffffffu, m1, 1));
        m1 = fmaxf(m1, __shfl_xor_sync(0xffffffffu, m1, 2));
        if ((lane & 3) == 0) {
            atomicMax(&rowmax_s[r0], ford(m0));
            atomicMax(&rowmax_s[r1], ford(m1));
        }
        if (t < NN / CT - 1) CPA_WAIT0();
        __syncthreads();   // rowmax visible to all; B prefetch landed

        // ---- phase B: append candidates above (rowmax - margin) ------------
        int ncol = t * CT + wn * 32 + cpair;
        float thr0 = unford(rowmax_s[r0]) - marg_s[r0];
        float thr1 = unford(rowmax_s[r1]) - marg_s[r1];
        if (m0 > thr0) {
#pragma unroll
            for (int ni = 0; ni < 4; ni++) {
                if (acc[ni][0] > thr0) {
                    int p = atomicAdd(&cnt_s[r0], 1);
                    if (p < RCAP) list_s[r0 * RCAP + p] = ncol + ni * 8;
                }
                if (acc[ni][1] > thr0) {
                    int p = atomicAdd(&cnt_s[r0], 1);
                    if (p < RCAP) list_s[r0 * RCAP + p] = ncol + ni * 8 + 1;
                }
            }
        }
        if (m1 > thr1) {
#pragma unroll
            for (int ni = 0; ni < 4; ni++) {
                if (acc[ni][2] > thr1) {
                    int p = atomicAdd(&cnt_s[r1], 1);
                    if (p < RCAP) list_s[r1 * RCAP + p] = ncol + ni * 8;
                }
                if (acc[ni][3] > thr1) {
                    int p = atomicAdd(&cnt_s[r1], 1);
                    if (p < RCAP) list_s[r1 * RCAP + p] = ncol + ni * 8 + 1;
                }
            }
        }
    }
    __syncthreads();   // lists complete

    // ---- tail 1: exact fp32 rescore (one warp per row, 8 rows/warp) --------
    for (int rr = wid; rr < RT; rr += 8) {
        int row = rb + rr;
        const float4* xp = (const float4*)(x + (size_t)row * DD);
        float4 xa = xp[lane * 2], xb2 = xp[lane * 2 + 1];
        float bestv = -3.4e38f;
        int bestn = 0;
        int c = cnt_s[rr];
        if (c <= RCAP) {
            for (int i = 0; i < c; i++) {
                int n = list_s[rr * RCAP + i];
                const float4* ep = (const float4*)(g_ehat + (size_t)n * DD);
                float4 e0 = ep[lane * 2], e1 = ep[lane * 2 + 1];
                float p = xa.x * e0.x + xa.y * e0.y + xa.z * e0.z + xa.w * e0.w +
                          xb2.x * e1.x + xb2.y * e1.y + xb2.z * e1.z +
                          xb2.w * e1.w;
#pragma unroll
                for (int o = 16; o > 0; o >>= 1)
                    p += __shfl_xor_sync(0xffffffffu, p, o);
                if (p > bestv || (p == bestv && n < bestn)) { bestv = p; bestn = n; }
            }
        } else {
            // overflow fallback (provably correct, ~never taken): full scan
            for (int n = 0; n < NN; n++) {
                const float4* ep = (const float4*)(g_ehat + (size_t)n * DD);
                float4 e0 = ep[lane * 2], e1 = ep[lane * 2 + 1];
                float p = xa.x * e0.x + xa.y * e0.y + xa.z * e0.z + xa.w * e0.w +
                          xb2.x * e1.x + xb2.y * e1.y + xb2.z * e1.z +
                          xb2.w * e1.w;
#pragma unroll
                for (int o = 16; o > 0; o >>= 1)
                    p += __shfl_xor_sync(0xffffffffu, p, o);
                if (p > bestv || (p == bestv && n < bestn)) { bestv = p; bestn = n; }
            }
        }
        if (lane == 0) bestn_s[rr] = bestn;
    }
    __syncthreads();

    // ---- tail 2: projection / x_q / commit epilogue (warp per row) ---------
    for (int rr = wid; rr < RT; rr += 8) {
        int row = rb + rr;
        int idx = bestn_s[rr];
        const float4* xp = (const float4*)(x + (size_t)row * DD);
        const float4* ep = (const float4*)(e + (size_t)idx * DD);
        float4 xa = xp[lane * 2], xb2 = xp[lane * 2 + 1];
        float4 ea = ep[lane * 2], eb2 = ep[lane * 2 + 1];
        float s1 = xa.x * ea.x + xa.y * ea.y + xa.z * ea.z + xa.w * ea.w +
                   xb2.x * eb2.x + xb2.y * eb2.y + xb2.z * eb2.z + xb2.w * eb2.w;
        float s2 = ea.x * ea.x + ea.y * ea.y + ea.z * ea.z + ea.w * ea.w +
                   eb2.x * eb2.x + eb2.y * eb2.y + eb2.z * eb2.z + eb2.w * eb2.w;
        float s3 = xa.x * xa.x + xa.y * xa.y + xa.z * xa.z + xa.w * xa.w +
                   xb2.x * xb2.x + xb2.y * xb2.y + xb2.z * xb2.z + xb2.w * xb2.w;
#pragma unroll
        for (int o = 16; o > 0; o >>= 1) {
            s1 += __shfl_xor_sync(0xffffffffu, s1, o);
            s2 += __shfl_xor_sync(0xffffffffu, s2, o);
            s3 += __shfl_xor_sync(0xffffffffu, s3, o);
        }
        float dot = s1, csq = s2, xsq = s3;
        float scalar = dot / (csq + 1e-8f);
        float4 o0, o1;
        o0.x = xa.x + (scalar * ea.x - xa.x);
        o0.y = xa.y + (scalar * ea.y - xa.y);
        o0.z = xa.z + (scalar * ea.z - xa.z);
        o0.w = xa.w + (scalar * ea.w - xa.w);
        o1.x = xb2.x + (scalar * eb2.x - xb2.x);
        o1.y = xb2.y + (scalar * eb2.y - xb2.y);
        o1.z = xb2.z + (scalar * eb2.z - xb2.z);
        o1.w = xb2.w + (scalar * eb2.w - xb2.w);
        float4* op = (float4*)(out + (size_t)row * DD);
        op[lane * 2] = o0;
        op[lane * 2 + 1] = o1;
        if (lane == 0) {
            float pn = fabsf(scalar) * sqrtf(csq);
            float commit = (scalar * dot) /
                           (fmaxf(pn, 1e-8f) * fmaxf(sqrtf(xsq), 1e-8f));
            marg_s[rr] = 1.0f - commit;        // marg_s dead after mainloop
            out[(size_t)BB * DD + 1 + row] = (float)idx;
            out[(size_t)BB * DD + 1 + BB + row] = scalar;
        }
    }
    __syncthreads();

    // ---- loss partial: deterministic fixed-order sum of this CTA's rows ----
    if (tid == 0) {
        float s = 0.f;
#pragma unroll
        for (int i = 0; i < RT; i++) s += marg_s[i];
        g_part[blockIdx.x] = s;
    }
}

// ---------------- loss finalize: deterministic tree over 512 parts ---------
__global__ void loss_fin_kernel(float* __restrict__ out) {
    __shared__ float sh[256];
    int t = threadIdx.x;
    sh[t] = g_part[t] + g_part[t + 256];
    __syncthreads();
    for (int o = 128; o > 0; o >>= 1) {
        if (t < o) sh[t] += sh[t + o];
        __syncthreads();
    }
    if (t == 0) out[(size_t)BB * DD] = 0.25f * sh[0] / (float)BB;
}

// ---------------------------------------------------------------------------
extern "C" void kernel_launch(void* const* d_in, const int* in_sizes, int n_in,
                              void* d_out, int out_size) {
    const float* x = (const float*)d_in[0];
    const float* e = (const float*)d_in[1];
    float* out = (float*)d_out;

    cudaFuncSetAttribute(gemm_kernel,
                         cudaFuncAttributeMaxDynamicSharedMemorySize, DYN_SMEM);
    prep_e_kernel<<<NN / 8, 256>>>(e);
    gemm_kernel<<<BB / RT, 256, DYN_SMEM>>>(x, e, out);
    loss_fin_kernel<<<1, 256>>>(out);
}

// round 16
// speedup vs baseline: 2.8987x; 1.2015x over previous
#include <cuda_runtime.h>
#include <cuda_bf16.h>
#include <cstdint>
#include <math.h>

#define BB 32768
#define DD 256
#define NN 8192
#define RT 64          // rows per CTA tile
#define CT 64          // cols per B chunk
#define RCAP 60

// ---------------- scratch (__device__ globals; no allocation allowed) -------
__device__ __nv_bfloat16 g_eb[(size_t)NN * DD];    // bf16(e_hat)       4 MB
__device__ float         g_ehat[(size_t)NN * DD];  // e_hat fp32        8 MB
__device__ float g_part[512];

// ---------------- helpers ---------------------------------------------------
__device__ __forceinline__ unsigned ford(float f) {
    unsigned u = __float_as_uint(f);
    return (u & 0x80000000u) ? ~u : (u | 0x80000000u);
}
__device__ __forceinline__ float unford(unsigned u) {
    unsigned v = (u & 0x80000000u) ? (u & 0x7fffffffu) : ~u;
    return __uint_as_float(v);
}
__device__ __forceinline__ uint32_t s2u(const void* p) {
    uint32_t a;
    asm("{ .reg .u64 t; cvta.to.shared.u64 t, %1; cvt.u32.u64 %0, t; }"
        : "=r"(a) : "l"(p));
    return a;
}
// smem tile layout: rows x 256 bf16 (512 B/row), 16B units XOR-swizzled
__device__ __forceinline__ uint32_t soff(int row, int u) {
    return (uint32_t)(row * 512 + ((u ^ (row & 7)) << 4));
}
__device__ __forceinline__ void cpa16(uint32_t s, const void* g) {
    asm volatile("cp.async.cg.shared.global [%0], [%1], 16;" :: "r"(s), "l"(g));
}
#define CPA_COMMIT() asm volatile("cp.async.commit_group;" ::: "memory")
#define CPA_WAIT0()  asm volatile("cp.async.wait_group 0;" ::: "memory")

#define LDSM4(r0, r1, r2, r3, addr) \
    asm volatile("ldmatrix.sync.aligned.m8n8.x4.shared.b16 {%0,%1,%2,%3}, [%4];" \
                 : "=r"(r0), "=r"(r1), "=r"(r2), "=r"(r3) : "r"(addr))

#define MMA16816(d, a0, a1, a2, a3, b0, b1) \
    asm volatile("mma.sync.aligned.m16n8k16.row.col.f32.bf16.bf16.f32 " \
                 "{%0,%1,%2,%3}, {%4,%5,%6,%7}, {%8,%9}, {%0,%1,%2,%3};" \
                 : "+f"((d)[0]), "+f"((d)[1]), "+f"((d)[2]), "+f"((d)[3]) \
                 : "r"(a0), "r"(a1), "r"(a2), "r"(a3), "r"(b0), "r"(b1))

// ---------------- prep: normalize embedding --------------------------------
__global__ void prep_e_kernel(const float* __restrict__ e) {
    int w = threadIdx.x >> 5, lane = threadIdx.x & 31;
    int n = blockIdx.x * 8 + w;
    float v[8];
    float ss = 0.f;
#pragma unroll
    for (int j = 0; j < 8; j++) {
        v[j] = e[(size_t)n * DD + j * 32 + lane];
        ss += v[j] * v[j];
    }
#pragma unroll
    for (int o = 16; o > 0; o >>= 1) ss += __shfl_xor_sync(0xffffffffu, ss, o);
    float inv = 1.f / fmaxf(sqrtf(ss), 1e-12f);
#pragma unroll
    for (int j = 0; j < 8; j++) {
        float h = v[j] * inv;
        g_ehat[(size_t)n * DD + j * 32 + lane] = h;
        g_eb[(size_t)n * DD + j * 32 + lane] = __float2bfloat16(h);
    }
}

// ---- fused HMMA bf16 GEMM + capture + rescore + epilogue + loss partial ---
// smem: A 32KB | B0 32KB | B1 32KB | rowmax 256 | marg 256 | cnt 256 |
//       bestn 256 | lists 15360  => 114688 B (identical to the 594.5 config)
#define SM_B0 32768
#define SM_B1 65536
#define SM_RM 98304
#define SM_MG 98560
#define SM_CC 98816
#define SM_BI 99072
#define SM_CL 99328
#define DYN_SMEM (99328 + RCAP * RT * 4)

__global__ void __launch_bounds__(256) gemm_kernel(const float* __restrict__ x,
                                                   const float* __restrict__ e,
                                                   float* __restrict__ out) {
    extern __shared__ char sm[];
    uint32_t sA = s2u(sm);
    int tid = threadIdx.x, wid = tid >> 5, lane = tid & 31;
    int rb = blockIdx.x * RT;
    unsigned* rowmax_s = (unsigned*)(sm + SM_RM);
    float* marg_s = (float*)(sm + SM_MG);
    int* cnt_s = (int*)(sm + SM_CC);
    int* bestn_s = (int*)(sm + SM_BI);
    int* list_s = (int*)(sm + SM_CL);

    // -- prologue: B chunk 0 via cp.async; A tile fp32->bf16 in-CTA ----------
#pragma unroll
    for (int i = 0; i < 8; i++) {
        int q = tid + (i << 8);
        int row = q >> 5, u = q & 31;
        cpa16(sA + SM_B0 + soff(row, u), g_eb + (size_t)row * DD + u * 8);
    }
    CPA_COMMIT();

    {
        int row = tid >> 2, qq = tid & 3;      // 4 threads per row
        const float4* xp =
            (const float4*)(x + (size_t)(rb + row) * DD + qq * 64);
        float ss = 0.f;
#pragma unroll
        for (int j = 0; j < 8; j++) {
            float4 v0 = xp[2 * j], v1 = xp[2 * j + 1];
            ss += v0.x * v0.x + v0.y * v0.y + v0.z * v0.z + v0.w * v0.w +
                  v1.x * v1.x + v1.y * v1.y + v1.z * v1.z + v1.w * v1.w;
            uint4 st;
            __nv_bfloat162 h;
            h = __floats2bfloat162_rn(v0.x, v0.y); st.x = *(uint32_t*)&h;
            h = __floats2bfloat162_rn(v0.z, v0.w); st.y = *(uint32_t*)&h;
            h = __floats2bfloat162_rn(v1.x, v1.y); st.z = *(uint32_t*)&h;
            h = __floats2bfloat162_rn(v1.z, v1.w); st.w = *(uint32_t*)&h;
            *(uint4*)(sm + soff(row, qq * 8 + j)) = st;
        }
        ss += __shfl_xor_sync(0xffffffffu, ss, 1);
        ss += __shfl_xor_sync(0xffffffffu, ss, 2);
        if (qq == 0) {
            // bound on bf16-input dot error (~0.004*||x||) with >2x slack
            marg_s[row] = 0.01f * sqrtf(ss) + 0.02f;
            rowmax_s[row] = ford(-3.4e38f);
            cnt_s[row] = 0;
        }
    }
    CPA_WAIT0();
    __syncthreads();

    int wm = wid >> 1, wn = wid & 1;           // 4 row-groups x 2 col-groups
    int g = lane >> 2, cpair = (lane & 3) * 2;

    // per-lane ldmatrix row/ku components
    int la7 = lane & 7;
    int rowA = wm * 16 + la7 + ((lane >> 3) & 1) * 8;
    int kuA_c = (lane >> 4);
    int rowB_c = wn * 32 + la7 + ((lane >> 4) & 1) * 8;  // + h*16
    int kuB_c = (lane >> 3) & 1;
    int r0 = wm * 16 + g, r1 = r0 + 8;

    // ---- hoist A fragments: the A tile is invariant across all 128 tiles ---
    uint32_t afr[16][4];
#pragma unroll
    for (int ks = 0; ks < 16; ks++)
        LDSM4(afr[ks][0], afr[ks][1], afr[ks][2], afr[ks][3],
              sA + soff(rowA, ks * 2 + kuA_c));

    for (int t = 0; t < NN / CT; t++) {
        uint32_t sBc = sA + ((t & 1) ? SM_B1 : SM_B0);
        if (t < NN / CT - 1) {
            uint32_t sBn = sA + ((t & 1) ? SM_B0 : SM_B1);
            const __nv_bfloat16* gsrc = g_eb + (size_t)(t + 1) * CT * DD;
#pragma unroll
            for (int i = 0; i < 8; i++) {
                int q = tid + (i << 8);
                int row = q >> 5, u = q & 31;
                cpa16(sBn + soff(row, u), gsrc + (size_t)row * DD + u * 8);
            }
            CPA_COMMIT();
        }

        float acc[4][4];
#pragma unroll
        for (int ni = 0; ni < 4; ni++)
#pragma unroll
            for (int r = 0; r < 4; r++) acc[ni][r] = 0.f;

#pragma unroll
        for (int ks = 0; ks < 16; ks++) {
            int kb = ks * 2;
            uint32_t b[4][2];
#pragma unroll
            for (int h = 0; h < 2; h++) {
                uint32_t addr = sBc + soff(rowB_c + h * 16, kb + kuB_c);
                LDSM4(b[h * 2][0], b[h * 2][1], b[h * 2 + 1][0], b[h * 2 + 1][1],
                      addr);
            }
#pragma unroll
            for (int ni = 0; ni < 4; ni++)
                MMA16816(acc[ni], afr[ks][0], afr[ks][1], afr[ks][2],
                         afr[ks][3], b[ni][0], b[ni][1]);
        }

        // ---- phase A: per-row tile max -> smem rowmax ----------------------
        float m0 = -3.4e38f, m1 = -3.4e38f;
#pragma unroll
        for (int ni = 0; ni < 4; ni++) {
            m0 = fmaxf(m0, fmaxf(acc[ni][0], acc[ni][1]));
            m1 = fmaxf(m1, fmaxf(acc[ni][2], acc[ni][3]));
        }
        m0 = fmaxf(m0, __shfl_xor_sync(0xffffffffu, m0, 1));
        m0 = fmaxf(m0, __shfl_xor_sync(0xffffffffu, m0, 2));
        m1 = fmaxf(m1, __shfl_xor_sync(0xffffffffu, m1, 1));
        m1 = fmaxf(m1, __shfl_xor_sync(0xffffffffu, m1, 2));
        if ((lane & 3) == 0) {
            atomicMax(&rowmax_s[r0], ford(m0));
            atomicMax(&rowmax_s[r1], ford(m1));
        }
        if (t < NN / CT - 1) CPA_WAIT0();
        __syncthreads();   // rowmax visible to all; B prefetch landed

        // ---- phase B: append candidates above (rowmax - margin) ------------
        int ncol = t * CT + wn * 32 + cpair;
        float thr0 = unford(rowmax_s[r0]) - marg_s[r0];
        float thr1 = unford(rowmax_s[r1]) - marg_s[r1];
        if (m0 > thr0) {
#pragma unroll
            for (int ni = 0; ni < 4; ni++) {
                if (acc[ni][0] > thr0) {
                    int p = atomicAdd(&cnt_s[r0], 1);
                    if (p < RCAP) list_s[r0 * RCAP + p] = ncol + ni * 8;
                }
                if (acc[ni][1] > thr0) {
                    int p = atomicAdd(&cnt_s[r0], 1);
                    if (p < RCAP) list_s[r0 * RCAP + p] = ncol + ni * 8 + 1;
                }
            }
        }
        if (m1 > thr1) {
#pragma unroll
            for (int ni = 0; ni < 4; ni++) {
                if (acc[ni][2] > thr1) {
                    int p = atomicAdd(&cnt_s[r1], 1);
                    if (p < RCAP) list_s[r1 * RCAP + p] = ncol + ni * 8;
                }
                if (acc[ni][3] > thr1) {
                    int p = atomicAdd(&cnt_s[r1], 1);
                    if (p < RCAP) list_s[r1 * RCAP + p] = ncol + ni * 8 + 1;
                }
            }
        }
    }
    __syncthreads();   // lists complete

    // ---- tail 1: exact fp32 rescore (one warp per row, 8 rows/warp) --------
    for (int rr = wid; rr < RT; rr += 8) {
        int row = rb + rr;
        const float4* xp = (const float4*)(x + (size_t)row * DD);
        float4 xa = xp[lane * 2], xb2 = xp[lane * 2 + 1];
        float bestv = -3.4e38f;
        int bestn = 0;
        int c = cnt_s[rr];
        if (c <= RCAP) {
            for (int i = 0; i < c; i++) {
                int n = list_s[rr * RCAP + i];
                const float4* ep = (const float4*)(g_ehat + (size_t)n * DD);
                float4 e0 = ep[lane * 2], e1 = ep[lane * 2 + 1];
                float p = xa.x * e0.x + xa.y * e0.y + xa.z * e0.z + xa.w * e0.w +
                          xb2.x * e1.x + xb2.y * e1.y + xb2.z * e1.z +
                          xb2.w * e1.w;
#pragma unroll
                for (int o = 16; o > 0; o >>= 1)
                    p += __shfl_xor_sync(0xffffffffu, p, o);
                if (p > bestv || (p == bestv && n < bestn)) { bestv = p; bestn = n; }
            }
        } else {
            // overflow fallback (provably correct, ~never taken): full scan
            for (int n = 0; n < NN; n++) {
                const float4* ep = (const float4*)(g_ehat + (size_t)n * DD);
                float4 e0 = ep[lane * 2], e1 = ep[lane * 2 + 1];
                float p = xa.x * e0.x + xa.y * e0.y + xa.z * e0.z + xa.w * e0.w +
                          xb2.x * e1.x + xb2.y * e1.y + xb2.z * e1.z +
                          xb2.w * e1.w;
#pragma unroll
                for (int o = 16; o > 0; o >>= 1)
                    p += __shfl_xor_sync(0xffffffffu, p, o);
                if (p > bestv || (p == bestv && n < bestn)) { bestv = p; bestn = n; }
            }
        }
        if (lane == 0) bestn_s[rr] = bestn;
    }
    __syncthreads();

    // ---- tail 2: projection / x_q / commit epilogue (warp per row) ---------
    for (int rr = wid; rr < RT; rr += 8) {
        int row = rb + rr;
        int idx = bestn_s[rr];
        const float4* xp = (const float4*)(x + (size_t)row * DD);
        const float4* ep = (const float4*)(e + (size_t)idx * DD);
        float4 xa = xp[lane * 2], xb2 = xp[lane * 2 + 1];
        float4 ea = ep[lane * 2], eb2 = ep[lane * 2 + 1];
        float s1 = xa.x * ea.x + xa.y * ea.y + xa.z * ea.z + xa.w * ea.w +
                   xb2.x * eb2.x + xb2.y * eb2.y + xb2.z * eb2.z + xb2.w * eb2.w;
        float s2 = ea.x * ea.x + ea.y * ea.y + ea.z * ea.z + ea.w * ea.w +
                   eb2.x * eb2.x + eb2.y * eb2.y + eb2.z * eb2.z + eb2.w * eb2.w;
        float s3 = xa.x * xa.x + xa.y * xa.y + xa.z * xa.z + xa.w * xa.w +
                   xb2.x * xb2.x + xb2.y * xb2.y + xb2.z * xb2.z + xb2.w * xb2.w;
#pragma unroll
        for (int o = 16; o > 0; o >>= 1) {
            s1 += __shfl_xor_sync(0xffffffffu, s1, o);
            s2 += __shfl_xor_sync(0xffffffffu, s2, o);
            s3 += __shfl_xor_sync(0xffffffffu, s3, o);
        }
        float dot = s1, csq = s2, xsq = s3;
        float scalar = dot / (csq + 1e-8f);
        float4 o0, o1;
        o0.x = xa.x + (scalar * ea.x - xa.x);
        o0.y = xa.y + (scalar * ea.y - xa.y);
        o0.z = xa.z + (scalar * ea.z - xa.z);
        o0.w = xa.w + (scalar * ea.w - xa.w);
        o1.x = xb2.x + (scalar * eb2.x - xb2.x);
        o1.y = xb2.y + (scalar * eb2.y - xb2.y);
        o1.z = xb2.z + (scalar * eb2.z - xb2.z);
        o1.w = xb2.w + (scalar * eb2.w - xb2.w);
        float4* op = (float4*)(out + (size_t)row * DD);
        op[lane * 2] = o0;
        op[lane * 2 + 1] = o1;
        if (lane == 0) {
            float pn = fabsf(scalar) * sqrtf(csq);
            float commit = (scalar * dot) /
                           (fmaxf(pn, 1e-8f) * fmaxf(sqrtf(xsq), 1e-8f));
            marg_s[rr] = 1.0f - commit;        // marg_s dead after mainloop
            out[(size_t)BB * DD + 1 + row] = (float)idx;
            out[(size_t)BB * DD + 1 + BB + row] = scalar;
        }
    }
    __syncthreads();

    // ---- loss partial: deterministic fixed-order sum of this CTA's rows ----
    if (tid == 0) {
        float s = 0.f;
#pragma unroll
        for (int i = 0; i < RT; i++) s += marg_s[i];
        g_part[blockIdx.x] = s;
    }
}

// ---------------- loss finalize: deterministic tree over 512 parts ---------
__global__ void loss_fin_kernel(float* __restrict__ out) {
    __shared__ float sh[256];
    int t = threadIdx.x;
    sh[t] = g_part[t] + g_part[t + 256];
    __syncthreads();
    for (int o = 128; o > 0; o >>= 1) {
        if (t < o) sh[t] += sh[t + o];
        __syncthreads();
    }
    if (t == 0) out[(size_t)BB * DD] = 0.25f * sh[0] / (float)BB;
}

// ---------------------------------------------------------------------------
extern "C" void kernel_launch(void* const* d_in, const int* in_sizes, int n_in,
                              void* d_out, int out_size) {
    const float* x = (const float*)d_in[0];
    const float* e = (const float*)d_in[1];
    float* out = (float*)d_out;

    cudaFuncSetAttribute(gemm_kernel,
                         cudaFuncAttributeMaxDynamicSharedMemorySize, DYN_SMEM);
    prep_e_kernel<<<NN / 8, 256>>>(e);
    gemm_kernel<<<BB / RT, 256, DYN_SMEM>>>(x, e, out);
    loss_fin_kernel<<<1, 256>>>(out);
}